// round 1
// baseline (speedup 1.0000x reference)
#include <cuda_runtime.h>
#include <math.h>

#define TOK 32768
#define DMODEL 256
#define HFF 1024
#define QKVD 768
#define PK 768

// ---------------- scratch (no allocs allowed) ----------------
__device__ float g_patches[TOK * PK];
__device__ float g_pre[TOK * DMODEL];
__device__ float g_h0[TOK * DMODEL];
__device__ float g_hid[TOK * HFF];
__device__ float g_tmp[TOK * DMODEL];
__device__ float g_qkv[TOK * QKVD];
__device__ float g_h2[TOK * DMODEL];

// ---------------- im2col: x(32,3,512,512) -> patches(32768,768) ----------------
__global__ void im2col_kernel(const float* __restrict__ x) {
    int idx = blockIdx.x * blockDim.x + threadIdx.x;  // one float4; total TOK*192 exact
    int tok = idx / 192;
    int p4  = (idx % 192) * 4;
    int b = tok >> 10;
    int n = tok & 1023;
    int ph = n >> 5, pw = n & 31;
    int c = p4 >> 8;
    int r = p4 & 255;
    int py = r >> 4, px = r & 15;
    const float* src = x + (((size_t)(b * 3 + c) * 512 + ph * 16 + py) * 512 + pw * 16 + px);
    float4 v = *(const float4*)src;
    *(float4*)(g_patches + (size_t)tok * PK + p4) = v;
}

// ---------------- LayerNorm + sinusoidal PE (reads g_pre, writes g_h0) ----------------
__global__ void ln_pe_kernel(const float* __restrict__ w, const float* __restrict__ b) {
    int gt = blockIdx.x * 8 + (threadIdx.x >> 5);   // token
    int lane = threadIdx.x & 31;
    const float4* row = (const float4*)(g_pre + (size_t)gt * DMODEL);
    float4 v0 = row[lane];
    float4 v1 = row[lane + 32];
    float s  = v0.x + v0.y + v0.z + v0.w + v1.x + v1.y + v1.z + v1.w;
    float ss = v0.x*v0.x + v0.y*v0.y + v0.z*v0.z + v0.w*v0.w
             + v1.x*v1.x + v1.y*v1.y + v1.z*v1.z + v1.w*v1.w;
    #pragma unroll
    for (int off = 16; off >= 1; off >>= 1) {
        s  += __shfl_xor_sync(0xffffffffu, s, off);
        ss += __shfl_xor_sync(0xffffffffu, ss, off);
    }
    float mean = s * (1.0f / 256.0f);
    float var  = ss * (1.0f / 256.0f) - mean * mean;
    float rstd = rsqrtf(var + 1e-5f);
    int n = gt & 1023;
    float nf = (float)n;

    float4 wv0 = ((const float4*)w)[lane];
    float4 wv1 = ((const float4*)w)[lane + 32];
    float4 bv0 = ((const float4*)b)[lane];
    float4 bv1 = ((const float4*)b)[lane + 32];

    float4 o0, o1;
    int d0 = lane * 4;
    int d1 = 128 + lane * 4;
    const float C = -9.210340371976184f / 256.0f;   // -ln(10000)/256
    #pragma unroll
    for (int i = 0; i < 8; i++) {
        int d = (i < 4) ? (d0 + i) : (d1 + (i - 4));
        float xv = (i == 0) ? v0.x : (i == 1) ? v0.y : (i == 2) ? v0.z : (i == 3) ? v0.w
                 : (i == 4) ? v1.x : (i == 5) ? v1.y : (i == 6) ? v1.z : v1.w;
        float wv = (i == 0) ? wv0.x : (i == 1) ? wv0.y : (i == 2) ? wv0.z : (i == 3) ? wv0.w
                 : (i == 4) ? wv1.x : (i == 5) ? wv1.y : (i == 6) ? wv1.z : wv1.w;
        float bv = (i == 0) ? bv0.x : (i == 1) ? bv0.y : (i == 2) ? bv0.z : (i == 3) ? bv0.w
                 : (i == 4) ? bv1.x : (i == 5) ? bv1.y : (i == 6) ? bv1.z : bv1.w;
        float ang = nf * expf(C * (float)(d & ~1));
        float pe = (d & 1) ? cosf(ang) : sinf(ang);
        float o = (xv - mean) * rstd * wv + bv + pe;
        if      (i == 0) o0.x = o; else if (i == 1) o0.y = o; else if (i == 2) o0.z = o; else if (i == 3) o0.w = o;
        else if (i == 4) o1.x = o; else if (i == 5) o1.y = o; else if (i == 6) o1.z = o; else o1.w = o;
    }
    float4* orow = (float4*)(g_h0 + (size_t)gt * DMODEL);
    orow[lane]      = o0;
    orow[lane + 32] = o1;
}

// ---------------- generic SGEMM: C[M,N] = A[M,K] @ B[N,K]^T (+bias, gelu, +res) ----------------
__device__ __forceinline__ float gelu_f(float x) {
    return 0.5f * x * (1.0f + tanhf(0.7978845608028654f * (x + 0.044715f * x * x * x)));
}

template <bool GELU>
__global__ __launch_bounds__(256, 2)
void sgemm_kernel(const float* __restrict__ A, const float* __restrict__ Bm,
                  const float* __restrict__ bias, const float* __restrict__ res,
                  float* __restrict__ C, int M, int N, int K) {
    __shared__ float As[8][132];
    __shared__ float Bs[8][132];
    int t = threadIdx.x;
    int bx = blockIdx.x, by = blockIdx.y;
    int tx = t & 15, ty = t >> 4;
    int lrow = t >> 1;
    int lk   = (t & 1) * 4;
    const float* Aptr = A + (size_t)(by * 128 + lrow) * K + lk;
    const float* Bptr = Bm + (size_t)(bx * 128 + lrow) * K + lk;

    float acc[8][8];
    #pragma unroll
    for (int i = 0; i < 8; i++)
        #pragma unroll
        for (int j = 0; j < 8; j++) acc[i][j] = 0.0f;

    float4 a  = *(const float4*)(Aptr);
    float4 bb = *(const float4*)(Bptr);

    for (int kt = 0; kt < K; kt += 8) {
        As[lk + 0][lrow] = a.x;  As[lk + 1][lrow] = a.y;
        As[lk + 2][lrow] = a.z;  As[lk + 3][lrow] = a.w;
        Bs[lk + 0][lrow] = bb.x; Bs[lk + 1][lrow] = bb.y;
        Bs[lk + 2][lrow] = bb.z; Bs[lk + 3][lrow] = bb.w;
        __syncthreads();

        float4 an = a, bn = bb;
        if (kt + 8 < K) {
            an = *(const float4*)(Aptr + kt + 8);
            bn = *(const float4*)(Bptr + kt + 8);
        }

        #pragma unroll
        for (int k = 0; k < 8; k++) {
            float4 a0 = *(const float4*)&As[k][ty * 8];
            float4 a1 = *(const float4*)&As[k][ty * 8 + 4];
            float4 b0 = *(const float4*)&Bs[k][tx * 8];
            float4 b1 = *(const float4*)&Bs[k][tx * 8 + 4];
            float av[8] = {a0.x, a0.y, a0.z, a0.w, a1.x, a1.y, a1.z, a1.w};
            float bv[8] = {b0.x, b0.y, b0.z, b0.w, b1.x, b1.y, b1.z, b1.w};
            #pragma unroll
            for (int i = 0; i < 8; i++)
                #pragma unroll
                for (int j = 0; j < 8; j++)
                    acc[i][j] += av[i] * bv[j];
        }
        __syncthreads();
        a = an; bb = bn;
    }

    int crow0 = by * 128 + ty * 8;
    int ccol0 = bx * 128 + tx * 8;
    #pragma unroll
    for (int i = 0; i < 8; i++) {
        size_t rowoff = (size_t)(crow0 + i) * N + ccol0;
        #pragma unroll
        for (int jj = 0; jj < 8; jj += 4) {
            float4 v = make_float4(acc[i][jj], acc[i][jj + 1], acc[i][jj + 2], acc[i][jj + 3]);
            if (bias) {
                float4 bv = *(const float4*)(bias + ccol0 + jj);
                v.x += bv.x; v.y += bv.y; v.z += bv.z; v.w += bv.w;
            }
            if (GELU) {
                v.x = gelu_f(v.x); v.y = gelu_f(v.y); v.z = gelu_f(v.z); v.w = gelu_f(v.w);
            }
            if (res) {
                float4 rv = *(const float4*)(res + rowoff + jj);
                v.x += rv.x; v.y += rv.y; v.z += rv.z; v.w += rv.w;
            }
            *(float4*)(C + rowoff + jj) = v;
        }
    }
}

// ---------------- windowed attention: one block per (batch, window, head) ----------------
__global__ __launch_bounds__(256)
void attn_kernel(const float* __restrict__ qkv, float* __restrict__ out) {
    __shared__ float Qs[64][36], Ks[64][36], Vs[64][36];
    __shared__ float Ps[64][65];
    int blk = blockIdx.x;
    int h = blk & 7, wwin = (blk >> 3) & 15, b = blk >> 7;
    int base = b * 1024 + wwin * 64;
    int t = threadIdx.x;

    for (int i = t; i < 512; i += 256) {
        int row = i >> 3, dg = (i & 7) * 4;
        const float* src = qkv + (size_t)(base + row) * QKVD + h * 32 + dg;
        float4 q4 = *(const float4*)(src);
        float4 k4 = *(const float4*)(src + 256);
        float4 v4 = *(const float4*)(src + 512);
        *(float4*)&Qs[row][dg] = q4;
        *(float4*)&Ks[row][dg] = k4;
        *(float4*)&Vs[row][dg] = v4;
    }
    __syncthreads();

    // scores: 4x4 tile per thread
    int qt  = (t >> 4) * 4;
    int kt4 = (t & 15) * 4;
    float s[4][4];
    #pragma unroll
    for (int i = 0; i < 4; i++)
        #pragma unroll
        for (int j = 0; j < 4; j++) s[i][j] = 0.0f;

    #pragma unroll
    for (int d = 0; d < 32; d += 4) {
        float4 qv[4], kv[4];
        #pragma unroll
        for (int i = 0; i < 4; i++) qv[i] = *(const float4*)&Qs[qt + i][d];
        #pragma unroll
        for (int j = 0; j < 4; j++) kv[j] = *(const float4*)&Ks[kt4 + j][d];
        #pragma unroll
        for (int i = 0; i < 4; i++)
            #pragma unroll
            for (int j = 0; j < 4; j++)
                s[i][j] += qv[i].x * kv[j].x + qv[i].y * kv[j].y +
                           qv[i].z * kv[j].z + qv[i].w * kv[j].w;
    }
    const float scale = 0.17677669529663687f;  // 1/sqrt(32)
    #pragma unroll
    for (int i = 0; i < 4; i++) {
        #pragma unroll
        for (int j = 0; j < 4; j++) s[i][j] *= scale;
        float m = fmaxf(fmaxf(s[i][0], s[i][1]), fmaxf(s[i][2], s[i][3]));
        #pragma unroll
        for (int off = 8; off >= 1; off >>= 1)
            m = fmaxf(m, __shfl_xor_sync(0xffffffffu, m, off));
        float sum = 0.0f;
        #pragma unroll
        for (int j = 0; j < 4; j++) { s[i][j] = expf(s[i][j] - m); sum += s[i][j]; }
        #pragma unroll
        for (int off = 8; off >= 1; off >>= 1)
            sum += __shfl_xor_sync(0xffffffffu, sum, off);
        float inv = 1.0f / sum;
        #pragma unroll
        for (int j = 0; j < 4; j++) Ps[qt + i][kt4 + j] = s[i][j] * inv;
    }
    __syncthreads();

    // attn @ V: thread -> (q, 8 dims)
    int q = t >> 2, d0 = (t & 3) * 8;
    float acc[8];
    #pragma unroll
    for (int j = 0; j < 8; j++) acc[j] = 0.0f;
    #pragma unroll 4
    for (int k = 0; k < 64; k++) {
        float p = Ps[q][k];
        float4 v0 = *(const float4*)&Vs[k][d0];
        float4 v1 = *(const float4*)&Vs[k][d0 + 4];
        acc[0] += p * v0.x; acc[1] += p * v0.y; acc[2] += p * v0.z; acc[3] += p * v0.w;
        acc[4] += p * v1.x; acc[5] += p * v1.y; acc[6] += p * v1.z; acc[7] += p * v1.w;
    }
    float* dst = out + (size_t)(base + q) * DMODEL + h * 32 + d0;
    *(float4*)(dst)     = make_float4(acc[0], acc[1], acc[2], acc[3]);
    *(float4*)(dst + 4) = make_float4(acc[4], acc[5], acc[6], acc[7]);
}

// ---------------- launch ----------------
extern "C" void kernel_launch(void* const* d_in, const int* in_sizes, int n_in,
                              void* d_out, int out_size) {
    (void)in_sizes; (void)n_in; (void)out_size;
    const float* x      = (const float*)d_in[0];
    const float* conv_w = (const float*)d_in[1];
    const float* conv_b = (const float*)d_in[2];
    const float* ln_w   = (const float*)d_in[3];
    const float* ln_b   = (const float*)d_in[4];
    const float* qkv_w  = (const float*)d_in[5];
    const float* qkv_b  = (const float*)d_in[6];
    const float* proj_w = (const float*)d_in[7];
    const float* proj_b = (const float*)d_in[8];
    const float* ff_w1  = (const float*)d_in[9];
    const float* ff_b1  = (const float*)d_in[10];
    const float* ff_w2  = (const float*)d_in[11];
    const float* ff_b2  = (const float*)d_in[12];
    float* out = (float*)d_out;

    float *patches, *pre, *h0, *hid, *tmp, *qkvp, *h2;
    cudaGetSymbolAddress((void**)&patches, g_patches);
    cudaGetSymbolAddress((void**)&pre,     g_pre);
    cudaGetSymbolAddress((void**)&h0,      g_h0);
    cudaGetSymbolAddress((void**)&hid,     g_hid);
    cudaGetSymbolAddress((void**)&tmp,     g_tmp);
    cudaGetSymbolAddress((void**)&qkvp,    g_qkv);
    cudaGetSymbolAddress((void**)&h2,      g_h2);

    // 1) patch extraction + embed GEMM + LN + PE
    im2col_kernel<<<24576, 256>>>(x);
    sgemm_kernel<false><<<dim3(2, 256), 256>>>(patches, conv_w, conv_b, nullptr, pre, TOK, DMODEL, PK);
    ln_pe_kernel<<<4096, 256>>>(ln_w, ln_b);

    // 2) FFN #1
    sgemm_kernel<true ><<<dim3(8, 256), 256>>>(h0,  ff_w1, ff_b1, nullptr, hid, TOK, HFF, DMODEL);
    sgemm_kernel<false><<<dim3(2, 256), 256>>>(hid, ff_w2, ff_b2, nullptr, tmp, TOK, DMODEL, HFF);

    // 3) windowed attention (qkv -> attn -> proj + residual(h0))
    sgemm_kernel<false><<<dim3(6, 256), 256>>>(tmp, qkv_w, qkv_b, nullptr, qkvp, TOK, QKVD, DMODEL);
    attn_kernel<<<4096, 256>>>(qkvp, tmp);
    sgemm_kernel<false><<<dim3(2, 256), 256>>>(tmp, proj_w, proj_b, h0, h2, TOK, DMODEL, DMODEL);

    // 4) FFN #2 + residual(h2) -> d_out
    sgemm_kernel<true ><<<dim3(8, 256), 256>>>(h2,  ff_w1, ff_b1, nullptr, hid, TOK, HFF, DMODEL);
    sgemm_kernel<false><<<dim3(2, 256), 256>>>(hid, ff_w2, ff_b2, h2, out, TOK, DMODEL, HFF);
}

// round 3
// speedup vs baseline: 1.0738x; 1.0738x over previous
#include <cuda_runtime.h>
#include <math.h>

#define TOK 32768
#define DMODEL 256
#define HFF 1024
#define QKVD 768
#define PK 768

// ---------------- scratch (no allocs allowed) ----------------
__device__ float g_patches[TOK * PK];
__device__ float g_pre[TOK * DMODEL];
__device__ float g_h0[TOK * DMODEL];
__device__ float g_hid[TOK * HFF];
__device__ float g_tmp[TOK * DMODEL];
__device__ float g_qkv[TOK * QKVD];
__device__ float g_h2[TOK * DMODEL];

// ---------------- im2col: x(32,3,512,512) -> patches(32768,768) ----------------
__global__ void im2col_kernel(const float* __restrict__ x) {
    int idx = blockIdx.x * blockDim.x + threadIdx.x;  // one float4; total TOK*192 exact
    int tok = idx / 192;
    int p4  = (idx % 192) * 4;
    int b = tok >> 10;
    int n = tok & 1023;
    int ph = n >> 5, pw = n & 31;
    int c = p4 >> 8;
    int r = p4 & 255;
    int py = r >> 4, px = r & 15;
    const float* src = x + (((size_t)(b * 3 + c) * 512 + ph * 16 + py) * 512 + pw * 16 + px);
    float4 v = *(const float4*)src;
    *(float4*)(g_patches + (size_t)tok * PK + p4) = v;
}

// ---------------- LayerNorm + sinusoidal PE (reads g_pre, writes g_h0) ----------------
__global__ void ln_pe_kernel(const float* __restrict__ w, const float* __restrict__ b) {
    int gt = blockIdx.x * 8 + (threadIdx.x >> 5);   // token
    int lane = threadIdx.x & 31;
    const float4* row = (const float4*)(g_pre + (size_t)gt * DMODEL);
    float4 v0 = row[lane];
    float4 v1 = row[lane + 32];
    float s  = v0.x + v0.y + v0.z + v0.w + v1.x + v1.y + v1.z + v1.w;
    float ss = v0.x*v0.x + v0.y*v0.y + v0.z*v0.z + v0.w*v0.w
             + v1.x*v1.x + v1.y*v1.y + v1.z*v1.z + v1.w*v1.w;
    #pragma unroll
    for (int off = 16; off >= 1; off >>= 1) {
        s  += __shfl_xor_sync(0xffffffffu, s, off);
        ss += __shfl_xor_sync(0xffffffffu, ss, off);
    }
    float mean = s * (1.0f / 256.0f);
    float var  = ss * (1.0f / 256.0f) - mean * mean;
    float rstd = rsqrtf(var + 1e-5f);
    int n = gt & 1023;
    float nf = (float)n;

    float4 wv0 = ((const float4*)w)[lane];
    float4 wv1 = ((const float4*)w)[lane + 32];
    float4 bv0 = ((const float4*)b)[lane];
    float4 bv1 = ((const float4*)b)[lane + 32];

    float4 o0, o1;
    int d0 = lane * 4;
    int d1 = 128 + lane * 4;
    const float C = -9.210340371976184f / 256.0f;   // -ln(10000)/256
    #pragma unroll
    for (int i = 0; i < 8; i++) {
        int d = (i < 4) ? (d0 + i) : (d1 + (i - 4));
        float xv = (i == 0) ? v0.x : (i == 1) ? v0.y : (i == 2) ? v0.z : (i == 3) ? v0.w
                 : (i == 4) ? v1.x : (i == 5) ? v1.y : (i == 6) ? v1.z : v1.w;
        float wv = (i == 0) ? wv0.x : (i == 1) ? wv0.y : (i == 2) ? wv0.z : (i == 3) ? wv0.w
                 : (i == 4) ? wv1.x : (i == 5) ? wv1.y : (i == 6) ? wv1.z : wv1.w;
        float bv = (i == 0) ? bv0.x : (i == 1) ? bv0.y : (i == 2) ? bv0.z : (i == 3) ? bv0.w
                 : (i == 4) ? bv1.x : (i == 5) ? bv1.y : (i == 6) ? bv1.z : bv1.w;
        float ang = nf * expf(C * (float)(d & ~1));
        float pe = (d & 1) ? cosf(ang) : sinf(ang);
        float o = (xv - mean) * rstd * wv + bv + pe;
        if      (i == 0) o0.x = o; else if (i == 1) o0.y = o; else if (i == 2) o0.z = o; else if (i == 3) o0.w = o;
        else if (i == 4) o1.x = o; else if (i == 5) o1.y = o; else if (i == 6) o1.z = o; else o1.w = o;
    }
    float4* orow = (float4*)(g_h0 + (size_t)gt * DMODEL);
    orow[lane]      = o0;
    orow[lane + 32] = o1;
}

// ---------------- helpers ----------------
__device__ __forceinline__ float gelu_f(float x) {
    return 0.5f * x * (1.0f + tanhf(0.7978845608028654f * (x + 0.044715f * x * x * x)));
}

__device__ __forceinline__ float tf32_rna(float x) {
    unsigned u;
    asm("cvt.rna.tf32.f32 %0, %1;" : "=r"(u) : "f"(x));
    return __uint_as_float(u);
}

__device__ __forceinline__ void mma_tf32(float* d, const unsigned* a, const unsigned* b) {
    asm volatile(
        "mma.sync.aligned.m16n8k8.row.col.f32.tf32.tf32.f32 "
        "{%0,%1,%2,%3}, {%4,%5,%6,%7}, {%8,%9}, {%0,%1,%2,%3};\n"
        : "+f"(d[0]), "+f"(d[1]), "+f"(d[2]), "+f"(d[3])
        : "r"(a[0]), "r"(a[1]), "r"(a[2]), "r"(a[3]), "r"(b[0]), "r"(b[1]));
}

// ---------------- 3xTF32 tensor-core GEMM: C[M,N] = A[M,K] @ B[N,K]^T ----------------
// Block tile 128x128, Ktile=16. 8 warps in 2(m) x 4(n), warp tile 64x32.
// smem holds hi/lo tf32 split planes, k-major, padded stride 136 (conflict-free frag loads).
#define SMSTRIDE 136

template <bool GELU>
__global__ __launch_bounds__(256)
void tf32_gemm(const float* __restrict__ A, const float* __restrict__ Bm,
               const float* __restrict__ bias, const float* __restrict__ res,
               float* __restrict__ C, int M, int N, int K) {
    __shared__ float Ahi[16][SMSTRIDE], Alo[16][SMSTRIDE];
    __shared__ float Bhi[16][SMSTRIDE], Blo[16][SMSTRIDE];

    int t = threadIdx.x;
    int warp = t >> 5, lane = t & 31;
    int g = lane >> 2, t4 = lane & 3;
    int wm = (warp >> 2) * 64;   // warp m-offset within block tile
    int wn = (warp & 3) * 32;    // warp n-offset
    int bx = blockIdx.x, by = blockIdx.y;

    // global load mapping: each thread loads 8 consecutive k for one row (2 float4)
    int lrow = t >> 1;        // 0..127
    int lk   = (t & 1) * 8;   // 0 or 8
    const float* Ag = A  + (size_t)(by * 128 + lrow) * K + lk;
    const float* Bg = Bm + (size_t)(bx * 128 + lrow) * K + lk;

    float acc[4][4][4];
    #pragma unroll
    for (int i = 0; i < 4; i++)
        #pragma unroll
        for (int j = 0; j < 4; j++)
            #pragma unroll
            for (int c = 0; c < 4; c++) acc[i][j][c] = 0.0f;

    float4 av0 = *(const float4*)(Ag);
    float4 av1 = *(const float4*)(Ag + 4);
    float4 bv0 = *(const float4*)(Bg);
    float4 bv1 = *(const float4*)(Bg + 4);

    for (int kt = 0; kt < K; kt += 16) {
        // convert + store (split into hi/lo tf32 planes, transposed to k-major)
        {
            float va[8] = {av0.x, av0.y, av0.z, av0.w, av1.x, av1.y, av1.z, av1.w};
            float vb[8] = {bv0.x, bv0.y, bv0.z, bv0.w, bv1.x, bv1.y, bv1.z, bv1.w};
            #pragma unroll
            for (int i = 0; i < 8; i++) {
                float ah = tf32_rna(va[i]);
                Ahi[lk + i][lrow] = ah;
                Alo[lk + i][lrow] = va[i] - ah;
                float bh = tf32_rna(vb[i]);
                Bhi[lk + i][lrow] = bh;
                Blo[lk + i][lrow] = vb[i] - bh;
            }
        }
        __syncthreads();

        if (kt + 16 < K) {
            av0 = *(const float4*)(Ag + kt + 16);
            av1 = *(const float4*)(Ag + kt + 20);
            bv0 = *(const float4*)(Bg + kt + 16);
            bv1 = *(const float4*)(Bg + kt + 20);
        }

        #pragma unroll
        for (int ks = 0; ks < 2; ks++) {
            int kb = ks * 8;
            unsigned ah[4][4], al[4][4];
            #pragma unroll
            for (int mt = 0; mt < 4; mt++) {
                int m = wm + mt * 16 + g;
                ah[mt][0] = __float_as_uint(Ahi[kb + t4][m]);
                ah[mt][1] = __float_as_uint(Ahi[kb + t4][m + 8]);
                ah[mt][2] = __float_as_uint(Ahi[kb + t4 + 4][m]);
                ah[mt][3] = __float_as_uint(Ahi[kb + t4 + 4][m + 8]);
                al[mt][0] = __float_as_uint(Alo[kb + t4][m]);
                al[mt][1] = __float_as_uint(Alo[kb + t4][m + 8]);
                al[mt][2] = __float_as_uint(Alo[kb + t4 + 4][m]);
                al[mt][3] = __float_as_uint(Alo[kb + t4 + 4][m + 8]);
            }
            unsigned bh[4][2], bl[4][2];
            #pragma unroll
            for (int nt = 0; nt < 4; nt++) {
                int n = wn + nt * 8 + g;
                bh[nt][0] = __float_as_uint(Bhi[kb + t4][n]);
                bh[nt][1] = __float_as_uint(Bhi[kb + t4 + 4][n]);
                bl[nt][0] = __float_as_uint(Blo[kb + t4][n]);
                bl[nt][1] = __float_as_uint(Blo[kb + t4 + 4][n]);
            }
            #pragma unroll
            for (int mt = 0; mt < 4; mt++)
                #pragma unroll
                for (int nt = 0; nt < 4; nt++) {
                    mma_tf32(acc[mt][nt], ah[mt], bh[nt]);
                    mma_tf32(acc[mt][nt], ah[mt], bl[nt]);
                    mma_tf32(acc[mt][nt], al[mt], bh[nt]);
                }
        }
        __syncthreads();
    }

    // epilogue: c0,c1 -> (row, col..col+1); c2,c3 -> (row+8, col..col+1)
    #pragma unroll
    for (int mt = 0; mt < 4; mt++) {
        int row0 = by * 128 + wm + mt * 16 + g;
        #pragma unroll
        for (int nt = 0; nt < 4; nt++) {
            int col = bx * 128 + wn + nt * 8 + t4 * 2;
            float bx0 = 0.0f, bx1 = 0.0f;
            if (bias) { bx0 = bias[col]; bx1 = bias[col + 1]; }
            #pragma unroll
            for (int half = 0; half < 2; half++) {
                int row = row0 + half * 8;
                float v0 = acc[mt][nt][half * 2 + 0] + bx0;
                float v1 = acc[mt][nt][half * 2 + 1] + bx1;
                if (GELU) { v0 = gelu_f(v0); v1 = gelu_f(v1); }
                size_t off = (size_t)row * N + col;
                if (res) {
                    float2 rv = *(const float2*)(res + off);
                    v0 += rv.x; v1 += rv.y;
                }
                *(float2*)(C + off) = make_float2(v0, v1);
            }
        }
    }
}

// ---------------- windowed attention: one block per (batch, window, head) ----------------
__global__ __launch_bounds__(256)
void attn_kernel(const float* __restrict__ qkv, float* __restrict__ out) {
    __shared__ float Qs[64][36], Ks[64][36], Vs[64][36];
    __shared__ float Ps[64][65];
    int blk = blockIdx.x;
    int h = blk & 7, wwin = (blk >> 3) & 15, b = blk >> 7;
    int base = b * 1024 + wwin * 64;
    int t = threadIdx.x;

    for (int i = t; i < 512; i += 256) {
        int row = i >> 3, dg = (i & 7) * 4;
        const float* src = qkv + (size_t)(base + row) * QKVD + h * 32 + dg;
        float4 q4 = *(const float4*)(src);
        float4 k4 = *(const float4*)(src + 256);
        float4 v4 = *(const float4*)(src + 512);
        *(float4*)&Qs[row][dg] = q4;
        *(float4*)&Ks[row][dg] = k4;
        *(float4*)&Vs[row][dg] = v4;
    }
    __syncthreads();

    int qt  = (t >> 4) * 4;
    int kt4 = (t & 15) * 4;
    float s[4][4];
    #pragma unroll
    for (int i = 0; i < 4; i++)
        #pragma unroll
        for (int j = 0; j < 4; j++) s[i][j] = 0.0f;

    #pragma unroll
    for (int d = 0; d < 32; d += 4) {
        float4 qv[4], kv[4];
        #pragma unroll
        for (int i = 0; i < 4; i++) qv[i] = *(const float4*)&Qs[qt + i][d];
        #pragma unroll
        for (int j = 0; j < 4; j++) kv[j] = *(const float4*)&Ks[kt4 + j][d];
        #pragma unroll
        for (int i = 0; i < 4; i++)
            #pragma unroll
            for (int j = 0; j < 4; j++)
                s[i][j] += qv[i].x * kv[j].x + qv[i].y * kv[j].y +
                           qv[i].z * kv[j].z + qv[i].w * kv[j].w;
    }
    const float scale = 0.17677669529663687f;  // 1/sqrt(32)
    #pragma unroll
    for (int i = 0; i < 4; i++) {
        #pragma unroll
        for (int j = 0; j < 4; j++) s[i][j] *= scale;
        float m = fmaxf(fmaxf(s[i][0], s[i][1]), fmaxf(s[i][2], s[i][3]));
        #pragma unroll
        for (int off = 8; off >= 1; off >>= 1)
            m = fmaxf(m, __shfl_xor_sync(0xffffffffu, m, off));
        float sum = 0.0f;
        #pragma unroll
        for (int j = 0; j < 4; j++) { s[i][j] = expf(s[i][j] - m); sum += s[i][j]; }
        #pragma unroll
        for (int off = 8; off >= 1; off >>= 1)
            sum += __shfl_xor_sync(0xffffffffu, sum, off);
        float inv = 1.0f / sum;
        #pragma unroll
        for (int j = 0; j < 4; j++) Ps[qt + i][kt4 + j] = s[i][j] * inv;
    }
    __syncthreads();

    int q = t >> 2, d0 = (t & 3) * 8;
    float acc[8];
    #pragma unroll
    for (int j = 0; j < 8; j++) acc[j] = 0.0f;
    #pragma unroll 4
    for (int k = 0; k < 64; k++) {
        float p = Ps[q][k];
        float4 v0 = *(const float4*)&Vs[k][d0];
        float4 v1 = *(const float4*)&Vs[k][d0 + 4];
        acc[0] += p * v0.x; acc[1] += p * v0.y; acc[2] += p * v0.z; acc[3] += p * v0.w;
        acc[4] += p * v1.x; acc[5] += p * v1.y; acc[6] += p * v1.z; acc[7] += p * v1.w;
    }
    float* dst = out + (size_t)(base + q) * DMODEL + h * 32 + d0;
    *(float4*)(dst)     = make_float4(acc[0], acc[1], acc[2], acc[3]);
    *(float4*)(dst + 4) = make_float4(acc[4], acc[5], acc[6], acc[7]);
}

// ---------------- launch ----------------
extern "C" void kernel_launch(void* const* d_in, const int* in_sizes, int n_in,
                              void* d_out, int out_size) {
    (void)in_sizes; (void)n_in; (void)out_size;
    const float* x      = (const float*)d_in[0];
    const float* conv_w = (const float*)d_in[1];
    const float* conv_b = (const float*)d_in[2];
    const float* ln_w   = (const float*)d_in[3];
    const float* ln_b   = (const float*)d_in[4];
    const float* qkv_w  = (const float*)d_in[5];
    const float* qkv_b  = (const float*)d_in[6];
    const float* proj_w = (const float*)d_in[7];
    const float* proj_b = (const float*)d_in[8];
    const float* ff_w1  = (const float*)d_in[9];
    const float* ff_b1  = (const float*)d_in[10];
    const float* ff_w2  = (const float*)d_in[11];
    const float* ff_b2  = (const float*)d_in[12];
    float* out = (float*)d_out;

    float *patches, *pre, *h0, *hid, *tmp, *qkvp, *h2;
    cudaGetSymbolAddress((void**)&patches, g_patches);
    cudaGetSymbolAddress((void**)&pre,     g_pre);
    cudaGetSymbolAddress((void**)&h0,      g_h0);
    cudaGetSymbolAddress((void**)&hid,     g_hid);
    cudaGetSymbolAddress((void**)&tmp,     g_tmp);
    cudaGetSymbolAddress((void**)&qkvp,    g_qkv);
    cudaGetSymbolAddress((void**)&h2,      g_h2);

    // 1) patch extraction + embed GEMM + LN + PE
    im2col_kernel<<<24576, 256>>>(x);
    tf32_gemm<false><<<dim3(2, 256), 256>>>(patches, conv_w, conv_b, nullptr, pre, TOK, DMODEL, PK);
    ln_pe_kernel<<<4096, 256>>>(ln_w, ln_b);

    // 2) FFN #1
    tf32_gemm<true ><<<dim3(8, 256), 256>>>(h0,  ff_w1, ff_b1, nullptr, hid, TOK, HFF, DMODEL);
    tf32_gemm<false><<<dim3(2, 256), 256>>>(hid, ff_w2, ff_b2, nullptr, tmp, TOK, DMODEL, HFF);

    // 3) windowed attention (qkv -> attn -> proj + residual(h0))
    tf32_gemm<false><<<dim3(6, 256), 256>>>(tmp, qkv_w, qkv_b, nullptr, qkvp, TOK, QKVD, DMODEL);
    attn_kernel<<<4096, 256>>>(qkvp, tmp);
    tf32_gemm<false><<<dim3(2, 256), 256>>>(tmp, proj_w, proj_b, h0, h2, TOK, DMODEL, DMODEL);

    // 4) FFN #2 + residual(h2) -> d_out
    tf32_gemm<true ><<<dim3(8, 256), 256>>>(h2,  ff_w1, ff_b1, nullptr, hid, TOK, HFF, DMODEL);
    tf32_gemm<false><<<dim3(2, 256), 256>>>(hid, ff_w2, ff_b2, h2, out, TOK, DMODEL, HFF);
}

// round 4
// speedup vs baseline: 1.1865x; 1.1049x over previous
#include <cuda_runtime.h>
#include <math.h>

#define TOK 32768
#define DMODEL 256
#define HFF 1024
#define QKVD 768
#define PK 768

// ---------------- scratch (no allocs allowed) ----------------
__device__ float g_patches[TOK * PK];
__device__ float g_pre[TOK * DMODEL];
__device__ float g_h0[TOK * DMODEL];
__device__ float g_hid[TOK * HFF];
__device__ float g_tmp[TOK * DMODEL];
__device__ float g_qkv[TOK * QKVD];
__device__ float g_h2[TOK * DMODEL];

// ---------------- im2col: x(32,3,512,512) -> patches(32768,768) ----------------
__global__ void im2col_kernel(const float* __restrict__ x) {
    int idx = blockIdx.x * blockDim.x + threadIdx.x;  // one float4; total TOK*192 exact
    int tok = idx / 192;
    int p4  = (idx % 192) * 4;
    int b = tok >> 10;
    int n = tok & 1023;
    int ph = n >> 5, pw = n & 31;
    int c = p4 >> 8;
    int r = p4 & 255;
    int py = r >> 4, px = r & 15;
    const float* src = x + (((size_t)(b * 3 + c) * 512 + ph * 16 + py) * 512 + pw * 16 + px);
    float4 v = *(const float4*)src;
    *(float4*)(g_patches + (size_t)tok * PK + p4) = v;
}

// ---------------- LayerNorm + sinusoidal PE (reads g_pre, writes g_h0) ----------------
__global__ void ln_pe_kernel(const float* __restrict__ w, const float* __restrict__ b) {
    int gt = blockIdx.x * 8 + (threadIdx.x >> 5);   // token
    int lane = threadIdx.x & 31;
    const float4* row = (const float4*)(g_pre + (size_t)gt * DMODEL);
    float4 v0 = row[lane];
    float4 v1 = row[lane + 32];
    float s  = v0.x + v0.y + v0.z + v0.w + v1.x + v1.y + v1.z + v1.w;
    float ss = v0.x*v0.x + v0.y*v0.y + v0.z*v0.z + v0.w*v0.w
             + v1.x*v1.x + v1.y*v1.y + v1.z*v1.z + v1.w*v1.w;
    #pragma unroll
    for (int off = 16; off >= 1; off >>= 1) {
        s  += __shfl_xor_sync(0xffffffffu, s, off);
        ss += __shfl_xor_sync(0xffffffffu, ss, off);
    }
    float mean = s * (1.0f / 256.0f);
    float var  = ss * (1.0f / 256.0f) - mean * mean;
    float rstd = rsqrtf(var + 1e-5f);
    int n = gt & 1023;
    float nf = (float)n;

    float4 wv0 = ((const float4*)w)[lane];
    float4 wv1 = ((const float4*)w)[lane + 32];
    float4 bv0 = ((const float4*)b)[lane];
    float4 bv1 = ((const float4*)b)[lane + 32];

    float4 o0, o1;
    int d0 = lane * 4;
    int d1 = 128 + lane * 4;
    const float C = -9.210340371976184f / 256.0f;   // -ln(10000)/256
    #pragma unroll
    for (int i = 0; i < 8; i++) {
        int d = (i < 4) ? (d0 + i) : (d1 + (i - 4));
        float xv = (i == 0) ? v0.x : (i == 1) ? v0.y : (i == 2) ? v0.z : (i == 3) ? v0.w
                 : (i == 4) ? v1.x : (i == 5) ? v1.y : (i == 6) ? v1.z : v1.w;
        float wv = (i == 0) ? wv0.x : (i == 1) ? wv0.y : (i == 2) ? wv0.z : (i == 3) ? wv0.w
                 : (i == 4) ? wv1.x : (i == 5) ? wv1.y : (i == 6) ? wv1.z : wv1.w;
        float bv = (i == 0) ? bv0.x : (i == 1) ? bv0.y : (i == 2) ? bv0.z : (i == 3) ? bv0.w
                 : (i == 4) ? bv1.x : (i == 5) ? bv1.y : (i == 6) ? bv1.z : bv1.w;
        float ang = nf * expf(C * (float)(d & ~1));
        float pe = (d & 1) ? cosf(ang) : sinf(ang);
        float o = (xv - mean) * rstd * wv + bv + pe;
        if      (i == 0) o0.x = o; else if (i == 1) o0.y = o; else if (i == 2) o0.z = o; else if (i == 3) o0.w = o;
        else if (i == 4) o1.x = o; else if (i == 5) o1.y = o; else if (i == 6) o1.z = o; else o1.w = o;
    }
    float4* orow = (float4*)(g_h0 + (size_t)gt * DMODEL);
    orow[lane]      = o0;
    orow[lane + 32] = o1;
}

// ---------------- helpers ----------------
__device__ __forceinline__ float gelu_f(float x) {
    return 0.5f * x * (1.0f + tanhf(0.7978845608028654f * (x + 0.044715f * x * x * x)));
}

__device__ __forceinline__ float tf32_rna(float x) {
    unsigned u;
    asm("cvt.rna.tf32.f32 %0, %1;" : "=r"(u) : "f"(x));
    return __uint_as_float(u);
}

__device__ __forceinline__ void mma_tf32(float* d, const unsigned* a, const unsigned* b) {
    asm volatile(
        "mma.sync.aligned.m16n8k8.row.col.f32.tf32.tf32.f32 "
        "{%0,%1,%2,%3}, {%4,%5,%6,%7}, {%8,%9}, {%0,%1,%2,%3};\n"
        : "+f"(d[0]), "+f"(d[1]), "+f"(d[2]), "+f"(d[3])
        : "r"(a[0]), "r"(a[1]), "r"(a[2]), "r"(a[3]), "r"(b[0]), "r"(b[1]));
}

// ---------------- 3xTF32 tensor-core GEMM: C[M,N] = A[M,K] @ B[N,K]^T ----------------
// Block tile 128x128, Ktile=16, double-buffered smem, ONE sync per K-tile.
// 8 warps in 2(m) x 4(n), warp tile 64x32.
// smem planes (per buffer): Ahi, Alo, Bhi, Blo each [16][136] floats, k-major.
#define SMSTRIDE 136
#define PLANE (16 * SMSTRIDE)          // 2176 floats
#define BUFSZ (4 * PLANE)              // 8704 floats per buffer
#define GEMM_SMEM_BYTES (2 * BUFSZ * 4)  // 69632 bytes

__device__ __forceinline__ void cvt_store_tile(float* base, int lk, int lrow,
                                               const float4& av0, const float4& av1,
                                               const float4& bv0, const float4& bv1) {
    float va[8] = {av0.x, av0.y, av0.z, av0.w, av1.x, av1.y, av1.z, av1.w};
    float vb[8] = {bv0.x, bv0.y, bv0.z, bv0.w, bv1.x, bv1.y, bv1.z, bv1.w};
    #pragma unroll
    for (int i = 0; i < 8; i++) {
        int off = (lk + i) * SMSTRIDE + lrow;
        float ah = tf32_rna(va[i]);
        base[off]             = ah;           // Ahi
        base[PLANE + off]     = va[i] - ah;   // Alo
        float bh = tf32_rna(vb[i]);
        base[2 * PLANE + off] = bh;           // Bhi
        base[3 * PLANE + off] = vb[i] - bh;   // Blo
    }
}

template <bool GELU>
__global__ __launch_bounds__(256)
void tf32_gemm(const float* __restrict__ A, const float* __restrict__ Bm,
               const float* __restrict__ bias, const float* __restrict__ res,
               float* __restrict__ C, int M, int N, int K) {
    extern __shared__ float sm[];

    int t = threadIdx.x;
    int warp = t >> 5, lane = t & 31;
    int g = lane >> 2, t4 = lane & 3;
    int wm = (warp >> 2) * 64;   // warp m-offset within block tile
    int wn = (warp & 3) * 32;    // warp n-offset
    int bx = blockIdx.x, by = blockIdx.y;

    // global load mapping: each thread loads 8 consecutive k for one row (2 float4)
    int lrow = t >> 1;        // 0..127
    int lk   = (t & 1) * 8;   // 0 or 8
    const float* Ag = A  + (size_t)(by * 128 + lrow) * K + lk;
    const float* Bg = Bm + (size_t)(bx * 128 + lrow) * K + lk;

    float acc[4][4][4];
    #pragma unroll
    for (int i = 0; i < 4; i++)
        #pragma unroll
        for (int j = 0; j < 4; j++)
            #pragma unroll
            for (int c = 0; c < 4; c++) acc[i][j][c] = 0.0f;

    // prologue: tile 0 -> buffer 0
    float4 av0 = *(const float4*)(Ag);
    float4 av1 = *(const float4*)(Ag + 4);
    float4 bv0 = *(const float4*)(Bg);
    float4 bv1 = *(const float4*)(Bg + 4);
    cvt_store_tile(sm, lk, lrow, av0, av1, bv0, bv1);
    __syncthreads();

    int ntiles = K >> 4;
    int buf = 0;
    for (int it = 0; it < ntiles; it++) {
        float* base = sm + buf * BUFSZ;
        bool more = (it + 1 < ntiles);

        // issue global prefetch for next tile (latency hidden under mma below)
        if (more) {
            int kn = (it + 1) << 4;
            av0 = *(const float4*)(Ag + kn);
            av1 = *(const float4*)(Ag + kn + 4);
            bv0 = *(const float4*)(Bg + kn);
            bv1 = *(const float4*)(Bg + kn + 4);
        }

        const float* Ahi = base;
        const float* Alo = base + PLANE;
        const float* Bhi = base + 2 * PLANE;
        const float* Blo = base + 3 * PLANE;

        #pragma unroll
        for (int ks = 0; ks < 2; ks++) {
            int kb = ks * 8;
            unsigned ah[4][4], al[4][4];
            #pragma unroll
            for (int mt = 0; mt < 4; mt++) {
                int m = wm + mt * 16 + g;
                int o0 = (kb + t4) * SMSTRIDE + m;
                int o1 = (kb + t4 + 4) * SMSTRIDE + m;
                ah[mt][0] = __float_as_uint(Ahi[o0]);
                ah[mt][1] = __float_as_uint(Ahi[o0 + 8]);
                ah[mt][2] = __float_as_uint(Ahi[o1]);
                ah[mt][3] = __float_as_uint(Ahi[o1 + 8]);
                al[mt][0] = __float_as_uint(Alo[o0]);
                al[mt][1] = __float_as_uint(Alo[o0 + 8]);
                al[mt][2] = __float_as_uint(Alo[o1]);
                al[mt][3] = __float_as_uint(Alo[o1 + 8]);
            }
            unsigned bh[4][2], bl[4][2];
            #pragma unroll
            for (int nt = 0; nt < 4; nt++) {
                int n = wn + nt * 8 + g;
                int o0 = (kb + t4) * SMSTRIDE + n;
                int o1 = (kb + t4 + 4) * SMSTRIDE + n;
                bh[nt][0] = __float_as_uint(Bhi[o0]);
                bh[nt][1] = __float_as_uint(Bhi[o1]);
                bl[nt][0] = __float_as_uint(Blo[o0]);
                bl[nt][1] = __float_as_uint(Blo[o1]);
            }
            #pragma unroll
            for (int mt = 0; mt < 4; mt++)
                #pragma unroll
                for (int nt = 0; nt < 4; nt++) {
                    mma_tf32(acc[mt][nt], ah[mt], bh[nt]);
                    mma_tf32(acc[mt][nt], ah[mt], bl[nt]);
                    mma_tf32(acc[mt][nt], al[mt], bh[nt]);
                }
        }

        // convert + store next tile into the other buffer (overlaps with mma tail)
        if (more) {
            cvt_store_tile(sm + (buf ^ 1) * BUFSZ, lk, lrow, av0, av1, bv0, bv1);
            __syncthreads();   // single barrier per K-tile
        }
        buf ^= 1;
    }

    // epilogue: c0,c1 -> (row, col..col+1); c2,c3 -> (row+8, col..col+1)
    #pragma unroll
    for (int mt = 0; mt < 4; mt++) {
        int row0 = by * 128 + wm + mt * 16 + g;
        #pragma unroll
        for (int nt = 0; nt < 4; nt++) {
            int col = bx * 128 + wn + nt * 8 + t4 * 2;
            float bx0 = 0.0f, bx1 = 0.0f;
            if (bias) { bx0 = bias[col]; bx1 = bias[col + 1]; }
            #pragma unroll
            for (int half = 0; half < 2; half++) {
                int row = row0 + half * 8;
                float v0 = acc[mt][nt][half * 2 + 0] + bx0;
                float v1 = acc[mt][nt][half * 2 + 1] + bx1;
                if (GELU) { v0 = gelu_f(v0); v1 = gelu_f(v1); }
                size_t off = (size_t)row * N + col;
                if (res) {
                    float2 rv = *(const float2*)(res + off);
                    v0 += rv.x; v1 += rv.y;
                }
                *(float2*)(C + off) = make_float2(v0, v1);
            }
        }
    }
}

// ---------------- windowed attention: one block per (batch, window, head) ----------------
__global__ __launch_bounds__(256)
void attn_kernel(const float* __restrict__ qkv, float* __restrict__ out) {
    __shared__ float Qs[64][36], Ks[64][36], Vs[64][36];
    __shared__ float Ps[64][65];
    int blk = blockIdx.x;
    int h = blk & 7, wwin = (blk >> 3) & 15, b = blk >> 7;
    int base = b * 1024 + wwin * 64;
    int t = threadIdx.x;

    for (int i = t; i < 512; i += 256) {
        int row = i >> 3, dg = (i & 7) * 4;
        const float* src = qkv + (size_t)(base + row) * QKVD + h * 32 + dg;
        float4 q4 = *(const float4*)(src);
        float4 k4 = *(const float4*)(src + 256);
        float4 v4 = *(const float4*)(src + 512);
        *(float4*)&Qs[row][dg] = q4;
        *(float4*)&Ks[row][dg] = k4;
        *(float4*)&Vs[row][dg] = v4;
    }
    __syncthreads();

    int qt  = (t >> 4) * 4;
    int kt4 = (t & 15) * 4;
    float s[4][4];
    #pragma unroll
    for (int i = 0; i < 4; i++)
        #pragma unroll
        for (int j = 0; j < 4; j++) s[i][j] = 0.0f;

    #pragma unroll
    for (int d = 0; d < 32; d += 4) {
        float4 qv[4], kv[4];
        #pragma unroll
        for (int i = 0; i < 4; i++) qv[i] = *(const float4*)&Qs[qt + i][d];
        #pragma unroll
        for (int j = 0; j < 4; j++) kv[j] = *(const float4*)&Ks[kt4 + j][d];
        #pragma unroll
        for (int i = 0; i < 4; i++)
            #pragma unroll
            for (int j = 0; j < 4; j++)
                s[i][j] += qv[i].x * kv[j].x + qv[i].y * kv[j].y +
                           qv[i].z * kv[j].z + qv[i].w * kv[j].w;
    }
    const float scale = 0.17677669529663687f;  // 1/sqrt(32)
    #pragma unroll
    for (int i = 0; i < 4; i++) {
        #pragma unroll
        for (int j = 0; j < 4; j++) s[i][j] *= scale;
        float m = fmaxf(fmaxf(s[i][0], s[i][1]), fmaxf(s[i][2], s[i][3]));
        #pragma unroll
        for (int off = 8; off >= 1; off >>= 1)
            m = fmaxf(m, __shfl_xor_sync(0xffffffffu, m, off));
        float sum = 0.0f;
        #pragma unroll
        for (int j = 0; j < 4; j++) { s[i][j] = expf(s[i][j] - m); sum += s[i][j]; }
        #pragma unroll
        for (int off = 8; off >= 1; off >>= 1)
            sum += __shfl_xor_sync(0xffffffffu, sum, off);
        float inv = 1.0f / sum;
        #pragma unroll
        for (int j = 0; j < 4; j++) Ps[qt + i][kt4 + j] = s[i][j] * inv;
    }
    __syncthreads();

    int q = t >> 2, d0 = (t & 3) * 8;
    float acc[8];
    #pragma unroll
    for (int j = 0; j < 8; j++) acc[j] = 0.0f;
    #pragma unroll 4
    for (int k = 0; k < 64; k++) {
        float p = Ps[q][k];
        float4 v0 = *(const float4*)&Vs[k][d0];
        float4 v1 = *(const float4*)&Vs[k][d0 + 4];
        acc[0] += p * v0.x; acc[1] += p * v0.y; acc[2] += p * v0.z; acc[3] += p * v0.w;
        acc[4] += p * v1.x; acc[5] += p * v1.y; acc[6] += p * v1.z; acc[7] += p * v1.w;
    }
    float* dst = out + (size_t)(base + q) * DMODEL + h * 32 + d0;
    *(float4*)(dst)     = make_float4(acc[0], acc[1], acc[2], acc[3]);
    *(float4*)(dst + 4) = make_float4(acc[4], acc[5], acc[6], acc[7]);
}

// ---------------- launch ----------------
extern "C" void kernel_launch(void* const* d_in, const int* in_sizes, int n_in,
                              void* d_out, int out_size) {
    (void)in_sizes; (void)n_in; (void)out_size;
    const float* x      = (const float*)d_in[0];
    const float* conv_w = (const float*)d_in[1];
    const float* conv_b = (const float*)d_in[2];
    const float* ln_w   = (const float*)d_in[3];
    const float* ln_b   = (const float*)d_in[4];
    const float* qkv_w  = (const float*)d_in[5];
    const float* qkv_b  = (const float*)d_in[6];
    const float* proj_w = (const float*)d_in[7];
    const float* proj_b = (const float*)d_in[8];
    const float* ff_w1  = (const float*)d_in[9];
    const float* ff_b1  = (const float*)d_in[10];
    const float* ff_w2  = (const float*)d_in[11];
    const float* ff_b2  = (const float*)d_in[12];
    float* out = (float*)d_out;

    float *patches, *pre, *h0, *hid, *tmp, *qkvp, *h2;
    cudaGetSymbolAddress((void**)&patches, g_patches);
    cudaGetSymbolAddress((void**)&pre,     g_pre);
    cudaGetSymbolAddress((void**)&h0,      g_h0);
    cudaGetSymbolAddress((void**)&hid,     g_hid);
    cudaGetSymbolAddress((void**)&tmp,     g_tmp);
    cudaGetSymbolAddress((void**)&qkvp,    g_qkv);
    cudaGetSymbolAddress((void**)&h2,      g_h2);

    // allow >48KB dynamic smem for the GEMM (host-side attribute, not captured)
    static bool attr_done = false;
    if (!attr_done) {
        cudaFuncSetAttribute(tf32_gemm<false>, cudaFuncAttributeMaxDynamicSharedMemorySize, GEMM_SMEM_BYTES);
        cudaFuncSetAttribute(tf32_gemm<true >, cudaFuncAttributeMaxDynamicSharedMemorySize, GEMM_SMEM_BYTES);
        attr_done = true;
    }

    // 1) patch extraction + embed GEMM + LN + PE
    im2col_kernel<<<24576, 256>>>(x);
    tf32_gemm<false><<<dim3(2, 256), 256, GEMM_SMEM_BYTES>>>(patches, conv_w, conv_b, nullptr, pre, TOK, DMODEL, PK);
    ln_pe_kernel<<<4096, 256>>>(ln_w, ln_b);

    // 2) FFN #1
    tf32_gemm<true ><<<dim3(8, 256), 256, GEMM_SMEM_BYTES>>>(h0,  ff_w1, ff_b1, nullptr, hid, TOK, HFF, DMODEL);
    tf32_gemm<false><<<dim3(2, 256), 256, GEMM_SMEM_BYTES>>>(hid, ff_w2, ff_b2, nullptr, tmp, TOK, DMODEL, HFF);

    // 3) windowed attention (qkv -> attn -> proj + residual(h0))
    tf32_gemm<false><<<dim3(6, 256), 256, GEMM_SMEM_BYTES>>>(tmp, qkv_w, qkv_b, nullptr, qkvp, TOK, QKVD, DMODEL);
    attn_kernel<<<4096, 256>>>(qkvp, tmp);
    tf32_gemm<false><<<dim3(2, 256), 256, GEMM_SMEM_BYTES>>>(tmp, proj_w, proj_b, h0, h2, TOK, DMODEL, DMODEL);

    // 4) FFN #2 + residual(h2) -> d_out
    tf32_gemm<true ><<<dim3(8, 256), 256, GEMM_SMEM_BYTES>>>(h2,  ff_w1, ff_b1, nullptr, hid, TOK, HFF, DMODEL);
    tf32_gemm<false><<<dim3(2, 256), 256, GEMM_SMEM_BYTES>>>(hid, ff_w2, ff_b2, h2, out, TOK, DMODEL, HFF);
}

// round 5
// speedup vs baseline: 1.7631x; 1.4859x over previous
#include <cuda_runtime.h>
#include <cuda_bf16.h>
#include <math.h>

#define TOK 32768
#define DMODEL 256
#define HFF 1024
#define QKVD 768
#define PK 768

// ---------------- scratch (no allocs allowed) ----------------
__device__ float g_patches[TOK * PK];
__device__ float g_pre[TOK * DMODEL];
__device__ float g_h0[TOK * DMODEL];
__device__ float g_hid[TOK * HFF];
__device__ float g_tmp[TOK * DMODEL];
__device__ float g_qkv[TOK * QKVD];
__device__ float g_h2[TOK * DMODEL];

// ---------------- im2col: x(32,3,512,512) -> patches(32768,768) ----------------
__global__ void im2col_kernel(const float* __restrict__ x) {
    int idx = blockIdx.x * blockDim.x + threadIdx.x;  // one float4; total TOK*192 exact
    int tok = idx / 192;
    int p4  = (idx % 192) * 4;
    int b = tok >> 10;
    int n = tok & 1023;
    int ph = n >> 5, pw = n & 31;
    int c = p4 >> 8;
    int r = p4 & 255;
    int py = r >> 4, px = r & 15;
    const float* src = x + (((size_t)(b * 3 + c) * 512 + ph * 16 + py) * 512 + pw * 16 + px);
    float4 v = *(const float4*)src;
    *(float4*)(g_patches + (size_t)tok * PK + p4) = v;
}

// ---------------- LayerNorm + sinusoidal PE (reads g_pre, writes g_h0) ----------------
__global__ void ln_pe_kernel(const float* __restrict__ w, const float* __restrict__ b) {
    int gt = blockIdx.x * 8 + (threadIdx.x >> 5);   // token
    int lane = threadIdx.x & 31;
    const float4* row = (const float4*)(g_pre + (size_t)gt * DMODEL);
    float4 v0 = row[lane];
    float4 v1 = row[lane + 32];
    float s  = v0.x + v0.y + v0.z + v0.w + v1.x + v1.y + v1.z + v1.w;
    float ss = v0.x*v0.x + v0.y*v0.y + v0.z*v0.z + v0.w*v0.w
             + v1.x*v1.x + v1.y*v1.y + v1.z*v1.z + v1.w*v1.w;
    #pragma unroll
    for (int off = 16; off >= 1; off >>= 1) {
        s  += __shfl_xor_sync(0xffffffffu, s, off);
        ss += __shfl_xor_sync(0xffffffffu, ss, off);
    }
    float mean = s * (1.0f / 256.0f);
    float var  = ss * (1.0f / 256.0f) - mean * mean;
    float rstd = rsqrtf(var + 1e-5f);
    int n = gt & 1023;
    float nf = (float)n;

    float4 wv0 = ((const float4*)w)[lane];
    float4 wv1 = ((const float4*)w)[lane + 32];
    float4 bv0 = ((const float4*)b)[lane];
    float4 bv1 = ((const float4*)b)[lane + 32];

    float4 o0, o1;
    int d0 = lane * 4;
    int d1 = 128 + lane * 4;
    const float C = -9.210340371976184f / 256.0f;   // -ln(10000)/256
    #pragma unroll
    for (int i = 0; i < 8; i++) {
        int d = (i < 4) ? (d0 + i) : (d1 + (i - 4));
        float xv = (i == 0) ? v0.x : (i == 1) ? v0.y : (i == 2) ? v0.z : (i == 3) ? v0.w
                 : (i == 4) ? v1.x : (i == 5) ? v1.y : (i == 6) ? v1.z : v1.w;
        float wv = (i == 0) ? wv0.x : (i == 1) ? wv0.y : (i == 2) ? wv0.z : (i == 3) ? wv0.w
                 : (i == 4) ? wv1.x : (i == 5) ? wv1.y : (i == 6) ? wv1.z : wv1.w;
        float bv = (i == 0) ? bv0.x : (i == 1) ? bv0.y : (i == 2) ? bv0.z : (i == 3) ? bv0.w
                 : (i == 4) ? bv1.x : (i == 5) ? bv1.y : (i == 6) ? bv1.z : bv1.w;
        float ang = nf * expf(C * (float)(d & ~1));
        float pe = (d & 1) ? cosf(ang) : sinf(ang);
        float o = (xv - mean) * rstd * wv + bv + pe;
        if      (i == 0) o0.x = o; else if (i == 1) o0.y = o; else if (i == 2) o0.z = o; else if (i == 3) o0.w = o;
        else if (i == 4) o1.x = o; else if (i == 5) o1.y = o; else if (i == 6) o1.z = o; else o1.w = o;
    }
    float4* orow = (float4*)(g_h0 + (size_t)gt * DMODEL);
    orow[lane]      = o0;
    orow[lane + 32] = o1;
}

// ---------------- helpers ----------------
__device__ __forceinline__ float gelu_f(float x) {
    return 0.5f * x * (1.0f + tanhf(0.7978845608028654f * (x + 0.044715f * x * x * x)));
}

__device__ __forceinline__ void mma_bf16(float* d, const unsigned* a, const unsigned* b) {
    asm volatile(
        "mma.sync.aligned.m16n8k16.row.col.f32.bf16.bf16.f32 "
        "{%0,%1,%2,%3}, {%4,%5,%6,%7}, {%8,%9}, {%0,%1,%2,%3};\n"
        : "+f"(d[0]), "+f"(d[1]), "+f"(d[2]), "+f"(d[3])
        : "r"(a[0]), "r"(a[1]), "r"(a[2]), "r"(a[3]), "r"(b[0]), "r"(b[1]));
}

// split v into hi/lo bf16; pack pairs (k even = low half)
__device__ __forceinline__ void split2_pack(const float* v, unsigned* hi, unsigned* lo) {
    #pragma unroll
    for (int i = 0; i < 4; i++) {
        __nv_bfloat16 h0 = __float2bfloat16_rn(v[2*i]);
        __nv_bfloat16 h1 = __float2bfloat16_rn(v[2*i+1]);
        __nv_bfloat16 l0 = __float2bfloat16_rn(v[2*i]   - __bfloat162float(h0));
        __nv_bfloat16 l1 = __float2bfloat16_rn(v[2*i+1] - __bfloat162float(h1));
        __nv_bfloat162 hp = __halves2bfloat162(h0, h1);   // x=low=even k
        __nv_bfloat162 lp = __halves2bfloat162(l0, l1);
        hi[i] = *(unsigned*)&hp;
        lo[i] = *(unsigned*)&lp;
    }
}

// ---------------- 3xBF16 tensor-core GEMM: C[M,N] = A[M,K] @ B[N,K]^T ----------------
// Block tile 128x128, Ktile=16, double-buffered smem, ONE sync per K-tile.
// 8 warps in 2(m) x 4(n), warp tile 64x32.
// smem planes (per buffer): Ahi, Alo, Bhi, Blo, each [8][136] bf16x2 words
// (k-pair-major: word (k2, row) holds k=2*k2, 2*k2+1 for that row).
#define SMSTRIDE 136
#define PLANE (8 * SMSTRIDE)            // 1088 words
#define BUFSZ (4 * PLANE)               // 4352 words per buffer
#define GEMM_SMEM_BYTES (2 * BUFSZ * 4) // 34816 bytes

__device__ __forceinline__ void cvt_store_tile(unsigned* base, int lk, int lrow,
                                               const float4& av0, const float4& av1,
                                               const float4& bv0, const float4& bv1) {
    float va[8] = {av0.x, av0.y, av0.z, av0.w, av1.x, av1.y, av1.z, av1.w};
    float vb[8] = {bv0.x, bv0.y, bv0.z, bv0.w, bv1.x, bv1.y, bv1.z, bv1.w};
    unsigned ahi[4], alo[4], bhi[4], blo[4];
    split2_pack(va, ahi, alo);
    split2_pack(vb, bhi, blo);
    int k2 = lk >> 1;   // 0 or 4
    #pragma unroll
    for (int i = 0; i < 4; i++) {
        int off = (k2 + i) * SMSTRIDE + lrow;
        base[off]             = ahi[i];
        base[PLANE + off]     = alo[i];
        base[2 * PLANE + off] = bhi[i];
        base[3 * PLANE + off] = blo[i];
    }
}

template <bool GELU>
__global__ __launch_bounds__(256)
void mp_gemm(const float* __restrict__ A, const float* __restrict__ Bm,
             const float* __restrict__ bias, const float* __restrict__ res,
             float* __restrict__ C, int M, int N, int K) {
    extern __shared__ unsigned sm[];

    int t = threadIdx.x;
    int warp = t >> 5, lane = t & 31;
    int g = lane >> 2, t4 = lane & 3;
    int wm = (warp >> 2) * 64;   // warp m-offset within block tile
    int wn = (warp & 3) * 32;    // warp n-offset
    int bx = blockIdx.x, by = blockIdx.y;

    // global load mapping: each thread loads 8 consecutive k for one row
    int lrow = t >> 1;        // 0..127
    int lk   = (t & 1) * 8;   // 0 or 8
    const float* Ag = A  + (size_t)(by * 128 + lrow) * K + lk;
    const float* Bg = Bm + (size_t)(bx * 128 + lrow) * K + lk;

    float acc[4][4][4];
    #pragma unroll
    for (int i = 0; i < 4; i++)
        #pragma unroll
        for (int j = 0; j < 4; j++)
            #pragma unroll
            for (int c = 0; c < 4; c++) acc[i][j][c] = 0.0f;

    // prologue: tile 0 -> buffer 0
    float4 av0 = *(const float4*)(Ag);
    float4 av1 = *(const float4*)(Ag + 4);
    float4 bv0 = *(const float4*)(Bg);
    float4 bv1 = *(const float4*)(Bg + 4);
    cvt_store_tile(sm, lk, lrow, av0, av1, bv0, bv1);
    __syncthreads();

    int ntiles = K >> 4;
    int buf = 0;
    for (int it = 0; it < ntiles; it++) {
        unsigned* base = sm + buf * BUFSZ;
        bool more = (it + 1 < ntiles);

        // issue global prefetch for next tile (latency hidden under mma below)
        if (more) {
            int kn = (it + 1) << 4;
            av0 = *(const float4*)(Ag + kn);
            av1 = *(const float4*)(Ag + kn + 4);
            bv0 = *(const float4*)(Bg + kn);
            bv1 = *(const float4*)(Bg + kn + 4);
        }

        const unsigned* Ahi = base;
        const unsigned* Alo = base + PLANE;
        const unsigned* Bhi = base + 2 * PLANE;
        const unsigned* Blo = base + 3 * PLANE;

        // fragments for full k16 tile
        unsigned ah[4][4], al[4][4];
        #pragma unroll
        for (int mt = 0; mt < 4; mt++) {
            int m = wm + mt * 16 + g;
            int o0 = t4 * SMSTRIDE + m;
            int o1 = (t4 + 4) * SMSTRIDE + m;
            ah[mt][0] = Ahi[o0];
            ah[mt][1] = Ahi[o0 + 8];
            ah[mt][2] = Ahi[o1];
            ah[mt][3] = Ahi[o1 + 8];
            al[mt][0] = Alo[o0];
            al[mt][1] = Alo[o0 + 8];
            al[mt][2] = Alo[o1];
            al[mt][3] = Alo[o1 + 8];
        }
        unsigned bh[4][2], bl[4][2];
        #pragma unroll
        for (int nt = 0; nt < 4; nt++) {
            int n = wn + nt * 8 + g;
            int o0 = t4 * SMSTRIDE + n;
            int o1 = (t4 + 4) * SMSTRIDE + n;
            bh[nt][0] = Bhi[o0];
            bh[nt][1] = Bhi[o1];
            bl[nt][0] = Blo[o0];
            bl[nt][1] = Blo[o1];
        }
        #pragma unroll
        for (int mt = 0; mt < 4; mt++)
            #pragma unroll
            for (int nt = 0; nt < 4; nt++) {
                mma_bf16(acc[mt][nt], ah[mt], bh[nt]);
                mma_bf16(acc[mt][nt], ah[mt], bl[nt]);
                mma_bf16(acc[mt][nt], al[mt], bh[nt]);
            }

        // convert + store next tile into the other buffer (overlaps with mma tail)
        if (more) {
            cvt_store_tile(sm + (buf ^ 1) * BUFSZ, lk, lrow, av0, av1, bv0, bv1);
            __syncthreads();   // single barrier per K-tile
        }
        buf ^= 1;
    }

    // epilogue: c0,c1 -> (row, col..col+1); c2,c3 -> (row+8, col..col+1)
    #pragma unroll
    for (int mt = 0; mt < 4; mt++) {
        int row0 = by * 128 + wm + mt * 16 + g;
        #pragma unroll
        for (int nt = 0; nt < 4; nt++) {
            int col = bx * 128 + wn + nt * 8 + t4 * 2;
            float bx0 = 0.0f, bx1 = 0.0f;
            if (bias) { bx0 = bias[col]; bx1 = bias[col + 1]; }
            #pragma unroll
            for (int half = 0; half < 2; half++) {
                int row = row0 + half * 8;
                float v0 = acc[mt][nt][half * 2 + 0] + bx0;
                float v1 = acc[mt][nt][half * 2 + 1] + bx1;
                if (GELU) { v0 = gelu_f(v0); v1 = gelu_f(v1); }
                size_t off = (size_t)row * N + col;
                if (res) {
                    float2 rv = *(const float2*)(res + off);
                    v0 += rv.x; v1 += rv.y;
                }
                *(float2*)(C + off) = make_float2(v0, v1);
            }
        }
    }
}

// ---------------- windowed attention: one block per (batch, window, head) ----------------
__global__ __launch_bounds__(256)
void attn_kernel(const float* __restrict__ qkv, float* __restrict__ out) {
    __shared__ float Qs[64][36], Ks[64][36], Vs[64][36];
    __shared__ float Ps[64][65];
    int blk = blockIdx.x;
    int h = blk & 7, wwin = (blk >> 3) & 15, b = blk >> 7;
    int base = b * 1024 + wwin * 64;
    int t = threadIdx.x;

    for (int i = t; i < 512; i += 256) {
        int row = i >> 3, dg = (i & 7) * 4;
        const float* src = qkv + (size_t)(base + row) * QKVD + h * 32 + dg;
        float4 q4 = *(const float4*)(src);
        float4 k4 = *(const float4*)(src + 256);
        float4 v4 = *(const float4*)(src + 512);
        *(float4*)&Qs[row][dg] = q4;
        *(float4*)&Ks[row][dg] = k4;
        *(float4*)&Vs[row][dg] = v4;
    }
    __syncthreads();

    int qt  = (t >> 4) * 4;
    int kt4 = (t & 15) * 4;
    float s[4][4];
    #pragma unroll
    for (int i = 0; i < 4; i++)
        #pragma unroll
        for (int j = 0; j < 4; j++) s[i][j] = 0.0f;

    #pragma unroll
    for (int d = 0; d < 32; d += 4) {
        float4 qv[4], kv[4];
        #pragma unroll
        for (int i = 0; i < 4; i++) qv[i] = *(const float4*)&Qs[qt + i][d];
        #pragma unroll
        for (int j = 0; j < 4; j++) kv[j] = *(const float4*)&Ks[kt4 + j][d];
        #pragma unroll
        for (int i = 0; i < 4; i++)
            #pragma unroll
            for (int j = 0; j < 4; j++)
                s[i][j] += qv[i].x * kv[j].x + qv[i].y * kv[j].y +
                           qv[i].z * kv[j].z + qv[i].w * kv[j].w;
    }
    const float scale = 0.17677669529663687f;  // 1/sqrt(32)
    #pragma unroll
    for (int i = 0; i < 4; i++) {
        #pragma unroll
        for (int j = 0; j < 4; j++) s[i][j] *= scale;
        float m = fmaxf(fmaxf(s[i][0], s[i][1]), fmaxf(s[i][2], s[i][3]));
        #pragma unroll
        for (int off = 8; off >= 1; off >>= 1)
            m = fmaxf(m, __shfl_xor_sync(0xffffffffu, m, off));
        float sum = 0.0f;
        #pragma unroll
        for (int j = 0; j < 4; j++) { s[i][j] = expf(s[i][j] - m); sum += s[i][j]; }
        #pragma unroll
        for (int off = 8; off >= 1; off >>= 1)
            sum += __shfl_xor_sync(0xffffffffu, sum, off);
        float inv = 1.0f / sum;
        #pragma unroll
        for (int j = 0; j < 4; j++) Ps[qt + i][kt4 + j] = s[i][j] * inv;
    }
    __syncthreads();

    int q = t >> 2, d0 = (t & 3) * 8;
    float acc[8];
    #pragma unroll
    for (int j = 0; j < 8; j++) acc[j] = 0.0f;
    #pragma unroll 4
    for (int k = 0; k < 64; k++) {
        float p = Ps[q][k];
        float4 v0 = *(const float4*)&Vs[k][d0];
        float4 v1 = *(const float4*)&Vs[k][d0 + 4];
        acc[0] += p * v0.x; acc[1] += p * v0.y; acc[2] += p * v0.z; acc[3] += p * v0.w;
        acc[4] += p * v1.x; acc[5] += p * v1.y; acc[6] += p * v1.z; acc[7] += p * v1.w;
    }
    float* dst = out + (size_t)(base + q) * DMODEL + h * 32 + d0;
    *(float4*)(dst)     = make_float4(acc[0], acc[1], acc[2], acc[3]);
    *(float4*)(dst + 4) = make_float4(acc[4], acc[5], acc[6], acc[7]);
}

// ---------------- launch ----------------
extern "C" void kernel_launch(void* const* d_in, const int* in_sizes, int n_in,
                              void* d_out, int out_size) {
    (void)in_sizes; (void)n_in; (void)out_size;
    const float* x      = (const float*)d_in[0];
    const float* conv_w = (const float*)d_in[1];
    const float* conv_b = (const float*)d_in[2];
    const float* ln_w   = (const float*)d_in[3];
    const float* ln_b   = (const float*)d_in[4];
    const float* qkv_w  = (const float*)d_in[5];
    const float* qkv_b  = (const float*)d_in[6];
    const float* proj_w = (const float*)d_in[7];
    const float* proj_b = (const float*)d_in[8];
    const float* ff_w1  = (const float*)d_in[9];
    const float* ff_b1  = (const float*)d_in[10];
    const float* ff_w2  = (const float*)d_in[11];
    const float* ff_b2  = (const float*)d_in[12];
    float* out = (float*)d_out;

    float *patches, *pre, *h0, *hid, *tmp, *qkvp, *h2;
    cudaGetSymbolAddress((void**)&patches, g_patches);
    cudaGetSymbolAddress((void**)&pre,     g_pre);
    cudaGetSymbolAddress((void**)&h0,      g_h0);
    cudaGetSymbolAddress((void**)&hid,     g_hid);
    cudaGetSymbolAddress((void**)&tmp,     g_tmp);
    cudaGetSymbolAddress((void**)&qkvp,    g_qkv);
    cudaGetSymbolAddress((void**)&h2,      g_h2);

    // 1) patch extraction + embed GEMM + LN + PE
    im2col_kernel<<<24576, 256>>>(x);
    mp_gemm<false><<<dim3(2, 256), 256, GEMM_SMEM_BYTES>>>(patches, conv_w, conv_b, nullptr, pre, TOK, DMODEL, PK);
    ln_pe_kernel<<<4096, 256>>>(ln_w, ln_b);

    // 2) FFN #1
    mp_gemm<true ><<<dim3(8, 256), 256, GEMM_SMEM_BYTES>>>(h0,  ff_w1, ff_b1, nullptr, hid, TOK, HFF, DMODEL);
    mp_gemm<false><<<dim3(2, 256), 256, GEMM_SMEM_BYTES>>>(hid, ff_w2, ff_b2, nullptr, tmp, TOK, DMODEL, HFF);

    // 3) windowed attention (qkv -> attn -> proj + residual(h0))
    mp_gemm<false><<<dim3(6, 256), 256, GEMM_SMEM_BYTES>>>(tmp, qkv_w, qkv_b, nullptr, qkvp, TOK, QKVD, DMODEL);
    attn_kernel<<<4096, 256>>>(qkvp, tmp);
    mp_gemm<false><<<dim3(2, 256), 256, GEMM_SMEM_BYTES>>>(tmp, proj_w, proj_b, h0, h2, TOK, DMODEL, DMODEL);

    // 4) FFN #2 + residual(h2) -> d_out
    mp_gemm<true ><<<dim3(8, 256), 256, GEMM_SMEM_BYTES>>>(h2,  ff_w1, ff_b1, nullptr, hid, TOK, HFF, DMODEL);
    mp_gemm<false><<<dim3(2, 256), 256, GEMM_SMEM_BYTES>>>(hid, ff_w2, ff_b2, h2, out, TOK, DMODEL, HFF);
}